// round 16
// baseline (speedup 1.0000x reference)
#include <cuda_runtime.h>
#include <cuda_bf16.h>
#include <cstdint>

typedef unsigned int u32;
typedef unsigned long long ull;

// B=4096, N=64, FEAT=128, TIME=128, D_MODEL=256, N_HEAD=2, D_K=128

__device__ __nv_bfloat16 g_qh[4096 * 256];
__device__ __nv_bfloat16 g_ql[4096 * 256];
__device__ __nv_bfloat16 g_Mth[512 * 256];
__device__ __nv_bfloat16 g_Mtl[512 * 256];
__device__ __nv_bfloat16 g_Pth[256 * 512];
__device__ __nv_bfloat16 g_Ptl[256 * 512];
__device__ __nv_bfloat16 g_kbh[4096 * 512];
__device__ __nv_bfloat16 g_kbl[4096 * 512];
__device__ float g_qk[4096 * 512];
__device__ float g_x[4096 * 256];

__device__ __forceinline__ ull pk2(float x) {
  ull r; asm("mov.b64 %0,{%1,%1};" : "=l"(r) : "f"(x)); return r;
}
__device__ __forceinline__ void fma2(ull& d, ull a, ull b) {
  asm("fma.rn.f32x2 %0,%1,%2,%0;" : "+l"(d) : "l"(a), "l"(b));
}
__device__ __forceinline__ float2 upk(ull v) {
  float2 f; asm("mov.b64 {%0,%1},%2;" : "=f"(f.x), "=f"(f.y) : "l"(v)); return f;
}
__device__ __forceinline__ u32 smem_to_u32(const void* smem_ptr) {
  u32 addr;
  asm("{ .reg .u64 tmp; cvta.to.shared.u64 tmp, %1; cvt.u32.u64 %0, tmp; }"
      : "=r"(addr) : "l"(smem_ptr));
  return addr;
}
__device__ __forceinline__ void bf16_split(float v, __nv_bfloat16* h, __nv_bfloat16* l) {
  __nv_bfloat16 hh = __float2bfloat16(v);
  *h = hh;
  *l = __float2bfloat16(v - __bfloat162float(hh));
}

#define CP_ASYNC16(dst, src) \
  asm volatile("cp.async.cg.shared.global [%0], [%1], 16;" :: "r"(dst), "l"(src) : "memory")

#define LDSM4(r0, r1, r2, r3, addr) \
  asm volatile("ldmatrix.sync.aligned.m8n8.x4.shared.b16 {%0,%1,%2,%3}, [%4];" \
               : "=r"(r0), "=r"(r1), "=r"(r2), "=r"(r3) : "r"(addr))
#define LDSM2(r0, r1, addr) \
  asm volatile("ldmatrix.sync.aligned.m8n8.x2.shared.b16 {%0,%1}, [%2];" \
               : "=r"(r0), "=r"(r1) : "r"(addr))
#define MMA16816(c, a, b) \
  asm volatile("mma.sync.aligned.m16n8k16.row.col.f32.bf16.bf16.f32 " \
               "{%0,%1,%2,%3}, {%4,%5,%6,%7}, {%8,%9}, {%0,%1,%2,%3};" \
               : "+f"((c)[0]), "+f"((c)[1]), "+f"((c)[2]), "+f"((c)[3]) \
               : "r"((a)[0]), "r"((a)[1]), "r"((a)[2]), "r"((a)[3]), \
                 "r"((b)[0]), "r"((b)[1]))

// ---------------------------------------------------------------------------
// K0: precompute M^T, P^T as bf16 hi/lo.
// ---------------------------------------------------------------------------
__global__ __launch_bounds__(256) void k0_precompute(
    const float* __restrict__ w_qs, const float* __restrict__ w_ks,
    const float* __restrict__ w_vs, const float* __restrict__ fc_w) {
  extern __shared__ float s0[];
  float* As = s0;              // 64 x 132
  float* Bsm = s0 + 64 * 132;  // M: 64 x 132; P: 128 x 64
  int m = blockIdx.x, t = threadIdx.x;
  int ty = t >> 4, tx = t & 15;
  float acc[4][4] = {{0.f}};

  if (m < 32) {
    int h = m >> 4, kt = (m >> 2) & 3, ct = m & 3;
#pragma unroll
    for (int i = 0; i < 8; i++) {
      int e = t + i * 256, r = e >> 5, c4 = e & 31;
      *(float4*)&As[r * 132 + c4 * 4] =
          *(const float4*)&w_qs[(kt * 64 + r) * 256 + h * 128 + c4 * 4];
      *(float4*)&Bsm[r * 132 + c4 * 4] =
          *(const float4*)&w_ks[(ct * 64 + r) * 256 + h * 128 + c4 * 4];
    }
    __syncthreads();
    for (int d = 0; d < 128; d += 4) {
      float4 av[4], bv[4];
#pragma unroll
      for (int i = 0; i < 4; i++) { av[i] = *(const float4*)&As[(ty * 4 + i) * 132 + d]; }
#pragma unroll
      for (int j = 0; j < 4; j++) { bv[j] = *(const float4*)&Bsm[(tx * 4 + j) * 132 + d]; }
#pragma unroll
      for (int i = 0; i < 4; i++) {
#pragma unroll
        for (int j = 0; j < 4; j++) {
          acc[i][j] += av[i].x * bv[j].x + av[i].y * bv[j].y +
                       av[i].z * bv[j].z + av[i].w * bv[j].w;
        }
      }
    }
#pragma unroll
    for (int i = 0; i < 4; i++) {
#pragma unroll
      for (int j = 0; j < 4; j++) {
        int kg = kt * 64 + ty * 4 + i;
        int ng = h * 256 + ct * 64 + tx * 4 + j;
        bf16_split(acc[i][j], &g_Mth[ng * 256 + kg], &g_Mtl[ng * 256 + kg]);
      }
    }
  } else {
    int m2 = m - 32;
    int h = m2 >> 4, it = (m2 >> 2) & 3, jt = m2 & 3;
#pragma unroll
    for (int i = 0; i < 8; i++) {
      int e = t + i * 256, r = e >> 5, c4 = e & 31;
      *(float4*)&As[r * 132 + c4 * 4] =
          *(const float4*)&w_vs[(it * 64 + r) * 256 + h * 128 + c4 * 4];
    }
#pragma unroll
    for (int i = 0; i < 8; i++) {
      int e = t + i * 256, d = e >> 4, j4 = e & 15;
      *(float4*)&Bsm[d * 64 + j4 * 4] =
          *(const float4*)&fc_w[(h * 128 + d) * 256 + jt * 64 + j4 * 4];
    }
    __syncthreads();
    for (int d = 0; d < 128; d++) {
      float4 bv = *(const float4*)&Bsm[d * 64 + tx * 4];
      float av[4];
#pragma unroll
      for (int i = 0; i < 4; i++) { av[i] = As[(ty * 4 + i) * 132 + d]; }
#pragma unroll
      for (int i = 0; i < 4; i++) {
        acc[i][0] += av[i] * bv.x; acc[i][1] += av[i] * bv.y;
        acc[i][2] += av[i] * bv.z; acc[i][3] += av[i] * bv.w;
      }
    }
#pragma unroll
    for (int i = 0; i < 4; i++) {
#pragma unroll
      for (int j = 0; j < 4; j++) {
        int kg = h * 256 + it * 64 + ty * 4 + i;
        int ng = jt * 64 + tx * 4 + j;
        bf16_split(acc[i][j], &g_Pth[ng * 512 + kg], &g_Ptl[ng * 512 + kg]);
      }
    }
  }
}

// ---------------------------------------------------------------------------
// K0b: q_in -> bf16 hi/lo.
// ---------------------------------------------------------------------------
__global__ __launch_bounds__(256) void k0b_convq(const float* __restrict__ src,
                                                 const float* __restrict__ srct) {
  int idx = blockIdx.x * 256 + threadIdx.x;
  int b = idx >> 8, k = idx & 255;
  float v = (k < 128) ? src[b * 128 + k] : srct[b * 128 + k - 128];
  bf16_split(v, &g_qh[idx], &g_ql[idx]);
}

// ---------------------------------------------------------------------------
// KG: bf16-split warp-MMA GEMM (mma.sync m16n8k16). C[M,N] = A[M,K]@B[N,K]^T.
// CTA tile 128x128, warp tile 64x32, K-chunks of 32. 256 threads.
// ---------------------------------------------------------------------------
__global__ __launch_bounds__(256) void kg_wmma(
    const __nv_bfloat16* __restrict__ Ah, const __nv_bfloat16* __restrict__ Al,
    const __nv_bfloat16* __restrict__ Bh, const __nv_bfloat16* __restrict__ Bl,
    float* __restrict__ C, int K, int Nld) {
  __shared__ __nv_bfloat16 sAh[128 * 40];
  __shared__ __nv_bfloat16 sAl[128 * 40];
  __shared__ __nv_bfloat16 sBh[128 * 40];
  __shared__ __nv_bfloat16 sBl[128 * 40];
  int t = threadIdx.x, lane = t & 31, wid = t >> 5;
  int wm = wid >> 2, wn = wid & 3;  // warp grid 2 x 4
  int bm = blockIdx.x * 128, bn = blockIdx.y * 128;
  u32 baAh = smem_to_u32(sAh), baAl = smem_to_u32(sAl);
  u32 baBh = smem_to_u32(sBh), baBl = smem_to_u32(sBl);

  float c[4][4][4];
#pragma unroll
  for (int mi = 0; mi < 4; mi++) {
#pragma unroll
    for (int ni = 0; ni < 4; ni++) {
#pragma unroll
      for (int q = 0; q < 4; q++) { c[mi][ni][q] = 0.f; }
    }
  }

  uint4 pAh[2], pAl[2], pBh[2], pBl[2];
  int nch = K >> 5;

#pragma unroll
  for (int i = 0; i < 2; i++) {
    int e = t + i * 256, r = e >> 2, q = e & 3;
    pAh[i] = *(const uint4*)(Ah + (size_t)(bm + r) * K + q * 8);
    pAl[i] = *(const uint4*)(Al + (size_t)(bm + r) * K + q * 8);
    pBh[i] = *(const uint4*)(Bh + (size_t)(bn + r) * K + q * 8);
    pBl[i] = *(const uint4*)(Bl + (size_t)(bn + r) * K + q * 8);
  }

  for (int ch = 0; ch < nch; ch++) {
#pragma unroll
    for (int i = 0; i < 2; i++) {
      int e = t + i * 256, r = e >> 2, q = e & 3;
      *(uint4*)(sAh + r * 40 + q * 8) = pAh[i];
      *(uint4*)(sAl + r * 40 + q * 8) = pAl[i];
      *(uint4*)(sBh + r * 40 + q * 8) = pBh[i];
      *(uint4*)(sBl + r * 40 + q * 8) = pBl[i];
    }
    __syncthreads();
    if (ch + 1 < nch) {
#pragma unroll
      for (int i = 0; i < 2; i++) {
        int e = t + i * 256, r = e >> 2, q = e & 3;
        pAh[i] = *(const uint4*)(Ah + (size_t)(bm + r) * K + (ch + 1) * 32 + q * 8);
        pAl[i] = *(const uint4*)(Al + (size_t)(bm + r) * K + (ch + 1) * 32 + q * 8);
        pBh[i] = *(const uint4*)(Bh + (size_t)(bn + r) * K + (ch + 1) * 32 + q * 8);
        pBl[i] = *(const uint4*)(Bl + (size_t)(bn + r) * K + (ch + 1) * 32 + q * 8);
      }
    }
#pragma unroll
    for (int ks = 0; ks < 2; ks++) {
      u32 bro = (u32)((lane & 7) * 80 + ks * 32 + ((lane >> 3) & 1) * 16);
      u32 bh[4][2], bl[4][2];
#pragma unroll
      for (int ni = 0; ni < 4; ni++) {
        u32 boff = (u32)((wn * 32 + ni * 8) * 80) + bro;
        LDSM2(bh[ni][0], bh[ni][1], baBh + boff);
        LDSM2(bl[ni][0], bl[ni][1], baBl + boff);
      }
#pragma unroll
      for (int mi = 0; mi < 4; mi++) {
        u32 aro = (u32)((wm * 64 + mi * 16 + (lane & 15)) * 80 + ks * 32 +
                        (lane >> 4) * 16);
        u32 ah[4], al[4];
        LDSM4(ah[0], ah[1], ah[2], ah[3], baAh + aro);
        LDSM4(al[0], al[1], al[2], al[3], baAl + aro);
#pragma unroll
        for (int ni = 0; ni < 4; ni++) {
          MMA16816(c[mi][ni], ah, bh[ni]);
          MMA16816(c[mi][ni], ah, bl[ni]);
          MMA16816(c[mi][ni], al, bh[ni]);
        }
      }
    }
    __syncthreads();
  }

#pragma unroll
  for (int mi = 0; mi < 4; mi++) {
#pragma unroll
    for (int ni = 0; ni < 4; ni++) {
      int row0 = bm + wm * 64 + mi * 16 + (lane >> 2);
      int col = bn + wn * 32 + ni * 8 + (lane & 3) * 2;
      float2 v0 = make_float2(c[mi][ni][0], c[mi][ni][1]);
      float2 v1 = make_float2(c[mi][ni][2], c[mi][ni][3]);
      *(float2*)&C[(size_t)row0 * Nld + col] = v0;
      *(float2*)&C[(size_t)(row0 + 8) * Nld + col] = v1;
    }
  }
}

// ---------------------------------------------------------------------------
// K2: persistent attention, 4 batches per CTA, double-buffered cp.async.
// grid 1024, 1 CTA/SM (128 KB dynamic smem).
// ---------------------------------------------------------------------------
__global__ __launch_bounds__(256) void k2_attn(const float* __restrict__ seq,
                                               const float* __restrict__ seqt,
                                               const void* __restrict__ maskp,
                                               float* __restrict__ out) {
  extern __shared__ float ks[];  // 2 buffers x (64 x 256) floats
  __shared__ float aw[128];
  __shared__ float mflag[64];
  __shared__ int smode;

  int t = threadIdx.x;
  int w = t >> 5, l = t & 31;
  u32 ksb = smem_to_u32(ks);
  const float sc = 0.08838834764831843f;
  const int NB = 4;
  int b0 = blockIdx.x * NB;

  if (t == 0) {
    const unsigned int* mw = (const unsigned int*)maskp;
    int isInt = 1, isFloat = 1;
    for (int i = 0; i < 32; i++) {
      unsigned v = mw[i];
      if (v > 1u) { isInt = 0; }
      if (v != 0u && v != 0x3F800000u) { isFloat = 0; }
    }
    smode = isInt ? 0 : (isFloat ? 1 : 2);
  }

  // Issue batch 0 loads (group 0).
  {
    int b = b0;
    const float4* s4 = (const float4*)(seq + (long long)b * 8192);
    const float4* st4 = (const float4*)(seqt + (long long)b * 8192);
#pragma unroll
    for (int i = 0; i < 8; i++) {
      int e = t + i * 256, n = e >> 5, c4 = e & 31;
      u32 dst = ksb + (u32)(n * 256 + c4 * 4) * 4u;
      CP_ASYNC16(dst, s4 + e);
      u32 dst2 = ksb + (u32)(n * 256 + 128 + c4 * 4) * 4u;
      CP_ASYNC16(dst2, st4 + e);
    }
    asm volatile("cp.async.commit_group;" ::: "memory");
  }
  __syncthreads();  // smode visible

  for (int bi = 0; bi < NB; bi++) {
    int b = b0 + bi;
    int buf = bi & 1;
    u32 kbase = ksb + (u32)buf * 65536u;
    float* kbuf = ks + buf * 16384;

    // Prefetch next batch into the other buffer.
    if (bi + 1 < NB) {
      int bn_ = b + 1;
      int obuf = (bi + 1) & 1;
      u32 dbase = ksb + (u32)obuf * 65536u;
      const float4* s4 = (const float4*)(seq + (long long)bn_ * 8192);
      const float4* st4 = (const float4*)(seqt + (long long)bn_ * 8192);
#pragma unroll
      for (int i = 0; i < 8; i++) {
        int e = t + i * 256, n = e >> 5, c4 = e & 31;
        CP_ASYNC16(dbase + (u32)(n * 256 + c4 * 4) * 4u, s4 + e);
        CP_ASYNC16(dbase + (u32)(n * 256 + 128 + c4 * 4) * 4u, st4 + e);
      }
      asm volatile("cp.async.commit_group;" ::: "memory");
      asm volatile("cp.async.wait_group 1;" ::: "memory");
    } else {
      asm volatile("cp.async.wait_group 0;" ::: "memory");
    }

    // q + mask for this batch.
    const float4* qv = (const float4*)(g_qk + b * 512);
    float4 qA0 = qv[l], qB0 = qv[32 + l], qA1 = qv[64 + l], qB1 = qv[96 + l];
    if (t < 64) {
      int mode = smode, m;
      if (mode == 0)      { m = ((const int*)maskp)[b * 64 + t] != 0; }
      else if (mode == 1) { m = ((const float*)maskp)[b * 64 + t] != 0.f; }
      else                { m = ((const unsigned char*)maskp)[b * 64 + t] != 0; }
      mflag[t] = m ? 1.f : 0.f;
    }
    __syncthreads();  // keys ready + mflag visible

    // Logits from smem.
    const float4* ks4 = (const float4*)kbuf;
#pragma unroll
    for (int i = 0; i < 8; i++) {
      int n = w + 8 * i;
      float4 kA = ks4[n * 64 + l];
      float4 kB = ks4[n * 64 + 32 + l];
      float s0 = kA.x * qA0.x + kA.y * qA0.y + kA.z * qA0.z + kA.w * qA0.w +
                 kB.x * qB0.x + kB.y * qB0.y + kB.z * qB0.z + kB.w * qB0.w;
      float s1 = kA.x * qA1.x + kA.y * qA1.y + kA.z * qA1.z + kA.w * qA1.w +
                 kB.x * qB1.x + kB.y * qB1.y + kB.z * qB1.z + kB.w * qB1.w;
#pragma unroll
      for (int o = 16; o; o >>= 1) {
        s0 += __shfl_xor_sync(0xffffffffu, s0, o);
        s1 += __shfl_xor_sync(0xffffffffu, s1, o);
      }
      if (l == 0) {
        int masked = (mflag[n] != 0.f);
        aw[n] = masked ? -1e10f : s0 * sc;
        aw[64 + n] = masked ? -1e10f : s1 * sc;
      }
    }
    __syncthreads();

    if (w < 2) {
      float x0 = aw[w * 64 + l], x1 = aw[w * 64 + 32 + l];
      float m = fmaxf(x0, x1);
#pragma unroll
      for (int o = 16; o; o >>= 1) { m = fmaxf(m, __shfl_xor_sync(0xffffffffu, m, o)); }
      float e0 = __expf(x0 - m), e1 = __expf(x1 - m);
      float s = e0 + e1;
#pragma unroll
      for (int o = 16; o; o >>= 1) { s += __shfl_xor_sync(0xffffffffu, s, o); }
      float inv = 1.f / s;
      float a0 = e0 * inv, a1 = e1 * inv;
      aw[w * 64 + l] = a0;
      aw[w * 64 + 32 + l] = a1;
      out[524288 + (w * 4096 + b) * 64 + l] = a0;
      out[524288 + (w * 4096 + b) * 64 + 32 + l] = a1;
    }
    __syncthreads();

    // Weighted key sum: thread t owns dim t.
    float kb0 = 0.f, kb1 = 0.f;
#pragma unroll 8
    for (int n = 0; n < 64; n++) {
      float x = kbuf[n * 256 + t];
      kb0 += aw[n] * x;
      kb1 += aw[64 + n] * x;
    }
    bf16_split(kb0, &g_kbh[b * 512 + t], &g_kbl[b * 512 + t]);
    bf16_split(kb1, &g_kbh[b * 512 + 256 + t], &g_kbl[b * 512 + 256 + t]);
    __syncthreads();  // all reads of kbuf done before it is refilled
  }
}

// ---------------------------------------------------------------------------
// K3b: per 16-batch tile: g_x + fc_b + residual -> LN -> FFN -> out.
// ---------------------------------------------------------------------------
__global__ __launch_bounds__(256) void k3b_ffn(
    const float* __restrict__ src, const float* __restrict__ srct,
    const float* __restrict__ fc_b, const float* __restrict__ ln_g,
    const float* __restrict__ ln_b, const float* __restrict__ fc1_w,
    const float* __restrict__ fc1_b, const float* __restrict__ fc2_w,
    const float* __restrict__ fc2_b, float* __restrict__ out) {
  extern __shared__ float sm3[];
  float* xh = sm3;           // 16 x 388
  float* Bs = xh + 16 * 388; // 32 x 128
  float* hm = Bs + 4096;     // 16 x 132
  int bb = blockIdx.x * 16;
  int t = threadIdx.x;
  int w = t >> 5, l = t & 31;

#pragma unroll
  for (int i = 0; i < 4; i++) {
    int e = t + i * 256, r = e >> 6, c4 = e & 63;
    int gb = bb + r;
    float4 a = *(const float4*)&g_x[gb * 256 + c4 * 4];
    float4 fb = *(const float4*)&fc_b[c4 * 4];
    float4 rs = (c4 < 32) ? *(const float4*)&src[gb * 128 + c4 * 4]
                          : *(const float4*)&srct[gb * 128 + (c4 - 32) * 4];
    xh[r * 388 + c4 * 4 + 0] = a.x + fb.x + rs.x;
    xh[r * 388 + c4 * 4 + 1] = a.y + fb.y + rs.y;
    xh[r * 388 + c4 * 4 + 2] = a.z + fb.z + rs.z;
    xh[r * 388 + c4 * 4 + 3] = a.w + fb.w + rs.w;
  }
#pragma unroll
  for (int i = 0; i < 2; i++) {
    int e = t + i * 256, r = e >> 5, c4 = e & 31;
    *(float4*)&xh[r * 388 + 256 + c4 * 4] = *(const float4*)&src[(bb + r) * 128 + c4 * 4];
  }
  __syncthreads();

#pragma unroll
  for (int rr = 0; rr < 2; rr++) {
    int r = w * 2 + rr;
    float s1 = 0.f, s2 = 0.f;
#pragma unroll
    for (int q = 0; q < 8; q++) {
      float x = xh[r * 388 + l + 32 * q];
      s1 += x; s2 += x * x;
    }
#pragma unroll
    for (int o = 16; o; o >>= 1) {
      s1 += __shfl_xor_sync(0xffffffffu, s1, o);
      s2 += __shfl_xor_sync(0xffffffffu, s2, o);
    }
    float mu = s1 * (1.f / 256.f);
    float var = s2 * (1.f / 256.f) - mu * mu;
    float rs = rsqrtf(var + 1e-5f);
#pragma unroll
    for (int q = 0; q < 8; q++) {
      int c = l + 32 * q;
      float x = xh[r * 388 + c];
      xh[r * 388 + c] = (x - mu) * rs * ln_g[c] + ln_b[c];
    }
  }
  __syncthreads();

  int ty2 = w, tx2 = l;
  {
    ull acc00 = 0ull, acc01 = 0ull, acc10 = 0ull, acc11 = 0ull;
    float4 pb[4];
#pragma unroll
    for (int i = 0; i < 4; i++) {
      int e = t + i * 256, kk = e >> 5, c4 = e & 31;
      pb[i] = *(const float4*)&fc1_w[kk * 128 + c4 * 4];
    }
    for (int kt = 0; kt < 12; kt++) {
#pragma unroll
      for (int i = 0; i < 4; i++) {
        int e = t + i * 256, kk = e >> 5, c4 = e & 31;
        *(float4*)&Bs[kk * 128 + c4 * 4] = pb[i];
      }
      __syncthreads();
      if (kt < 11) {
#pragma unroll
        for (int i = 0; i < 4; i++) {
          int e = t + i * 256, kk = e >> 5, c4 = e & 31;
          pb[i] = *(const float4*)&fc1_w[((kt + 1) * 32 + kk) * 128 + c4 * 4];
        }
      }
#pragma unroll
      for (int kk = 0; kk < 32; kk++) {
        int k = kt * 32 + kk;
        ull A0 = pk2(xh[(ty2 * 2 + 0) * 388 + k]);
        ull A1 = pk2(xh[(ty2 * 2 + 1) * 388 + k]);
        ull b0 = *(const ull*)&Bs[kk * 128 + tx2 * 4];
        ull b1 = *(const ull*)&Bs[kk * 128 + tx2 * 4 + 2];
        fma2(acc00, A0, b0); fma2(acc01, A0, b1);
        fma2(acc10, A1, b0); fma2(acc11, A1, b1);
      }
      __syncthreads();
    }
    {
      float2 p0 = upk(acc00), p1 = upk(acc01);
      float2 p2 = upk(acc10), p3 = upk(acc11);
      int c = tx2 * 4;
      hm[(ty2 * 2 + 0) * 132 + c + 0] = fmaxf(p0.x + fc1_b[c + 0], 0.f);
      hm[(ty2 * 2 + 0) * 132 + c + 1] = fmaxf(p0.y + fc1_b[c + 1], 0.f);
      hm[(ty2 * 2 + 0) * 132 + c + 2] = fmaxf(p1.x + fc1_b[c + 2], 0.f);
      hm[(ty2 * 2 + 0) * 132 + c + 3] = fmaxf(p1.y + fc1_b[c + 3], 0.f);
      hm[(ty2 * 2 + 1) * 132 + c + 0] = fmaxf(p2.x + fc1_b[c + 0], 0.f);
      hm[(ty2 * 2 + 1) * 132 + c + 1] = fmaxf(p2.y + fc1_b[c + 1], 0.f);
      hm[(ty2 * 2 + 1) * 132 + c + 2] = fmaxf(p3.x + fc1_b[c + 2], 0.f);
      hm[(ty2 * 2 + 1) * 132 + c + 3] = fmaxf(p3.y + fc1_b[c + 3], 0.f);
    }
  }
  __syncthreads();

  {
    ull acc00 = 0ull, acc01 = 0ull, acc10 = 0ull, acc11 = 0ull;
    float4 pb[4];
#pragma unroll
    for (int i = 0; i < 4; i++) {
      int e = t + i * 256, kk = e >> 5, c4 = e & 31;
      pb[i] = *(const float4*)&fc2_w[kk * 128 + c4 * 4];
    }
    for (int kt = 0; kt < 4; kt++) {
#pragma unroll
      for (int i = 0; i < 4; i++) {
        int e = t + i * 256, kk = e >> 5, c4 = e & 31;
        *(float4*)&Bs[kk * 128 + c4 * 4] = pb[i];
      }
      __syncthreads();
      if (kt < 3) {
#pragma unroll
        for (int i = 0; i < 4; i++) {
          int e = t + i * 256, kk = e >> 5, c4 = e & 31;
          pb[i] = *(const float4*)&fc2_w[((kt + 1) * 32 + kk) * 128 + c4 * 4];
        }
      }
#pragma unroll
      for (int kk = 0; kk < 32; kk++) {
        int k = kt * 32 + kk;
        ull A0 = pk2(hm[(ty2 * 2 + 0) * 132 + k]);
        ull A1 = pk2(hm[(ty2 * 2 + 1) * 132 + k]);
        ull b0 = *(const ull*)&Bs[kk * 128 + tx2 * 4];
        ull b1 = *(const ull*)&Bs[kk * 128 + tx2 * 4 + 2];
        fma2(acc00, A0, b0); fma2(acc01, A0, b1);
        fma2(acc10, A1, b0); fma2(acc11, A1, b1);
      }
      __syncthreads();
    }
    {
      float2 p0 = upk(acc00), p1 = upk(acc01);
      float2 p2 = upk(acc10), p3 = upk(acc11);
      int c = tx2 * 4;
      int r0 = bb + ty2 * 2 + 0, r1 = bb + ty2 * 2 + 1;
      float4 v0 = make_float4(p0.x + fc2_b[c], p0.y + fc2_b[c + 1],
                              p1.x + fc2_b[c + 2], p1.y + fc2_b[c + 3]);
      float4 v1 = make_float4(p2.x + fc2_b[c], p2.y + fc2_b[c + 1],
                              p3.x + fc2_b[c + 2], p3.y + fc2_b[c + 3]);
      *(float4*)&out[r0 * 128 + c] = v0;
      *(float4*)&out[r1 * 128 + c] = v1;
    }
  }
}

// ---------------------------------------------------------------------------
extern "C" void kernel_launch(void* const* d_in, const int* in_sizes, int n_in,
                              void* d_out, int out_size) {
  const float* src   = (const float*)d_in[0];
  const float* src_t = (const float*)d_in[1];
  const float* seq   = (const float*)d_in[2];
  const float* seq_t = (const float*)d_in[3];
  const void*  mask  = d_in[4];
  const float* w_qs  = (const float*)d_in[5];
  const float* w_ks  = (const float*)d_in[6];
  const float* w_vs  = (const float*)d_in[7];
  const float* fc_w  = (const float*)d_in[8];
  const float* fc_b  = (const float*)d_in[9];
  const float* ln_g  = (const float*)d_in[10];
  const float* ln_b  = (const float*)d_in[11];
  const float* fc1_w = (const float*)d_in[12];
  const float* fc1_b = (const float*)d_in[13];
  const float* fc2_w = (const float*)d_in[14];
  const float* fc2_b = (const float*)d_in[15];
  float* out = (float*)d_out;

  const int K0_SMEM = (64 * 132 * 2) * 4;
  const int K2_SMEM = 2 * 64 * 256 * 4;  // 131072
  const int K3B_SMEM = (16 * 388 + 4096 + 16 * 132) * 4;
  cudaFuncSetAttribute(k0_precompute, cudaFuncAttributeMaxDynamicSharedMemorySize, K0_SMEM);
  cudaFuncSetAttribute(k2_attn, cudaFuncAttributeMaxDynamicSharedMemorySize, K2_SMEM);
  cudaFuncSetAttribute(k3b_ffn, cudaFuncAttributeMaxDynamicSharedMemorySize, K3B_SMEM);

  __nv_bfloat16 *qh, *ql, *Mth, *Mtl, *Pth, *Ptl, *kbh, *kbl;
  float *qk, *xx;
  cudaGetSymbolAddress((void**)&qh, g_qh);
  cudaGetSymbolAddress((void**)&ql, g_ql);
  cudaGetSymbolAddress((void**)&Mth, g_Mth);
  cudaGetSymbolAddress((void**)&Mtl, g_Mtl);
  cudaGetSymbolAddress((void**)&Pth, g_Pth);
  cudaGetSymbolAddress((void**)&Ptl, g_Ptl);
  cudaGetSymbolAddress((void**)&kbh, g_kbh);
  cudaGetSymbolAddress((void**)&kbl, g_kbl);
  cudaGetSymbolAddress((void**)&qk, g_qk);
  cudaGetSymbolAddress((void**)&xx, g_x);

  k0_precompute<<<64, 256, K0_SMEM>>>(w_qs, w_ks, w_vs, fc_w);
  k0b_convq<<<4096, 256>>>(src, src_t);
  kg_wmma<<<dim3(32, 4), 256>>>(qh, ql, Mth, Mtl, qk, 256, 512);
  k2_attn<<<1024, 256, K2_SMEM>>>(seq, seq_t, mask, out);
  kg_wmma<<<dim3(32, 2), 256>>>(kbh, kbl, Pth, Ptl, xx, 512, 256);
  k3b_ffn<<<256, 256, K3B_SMEM>>>(src, src_t, fc_b, ln_g, ln_b, fc1_w, fc1_b,
                                  fc2_w, fc2_b, out);
}

// round 17
// speedup vs baseline: 1.3706x; 1.3706x over previous
#include <cuda_runtime.h>
#include <cuda_bf16.h>
#include <cstdint>

typedef unsigned int u32;
typedef unsigned long long ull;

// B=4096, N=64, FEAT=128, TIME=128, D_MODEL=256, N_HEAD=2, D_K=128

__device__ __nv_bfloat16 g_qh[4096 * 256];
__device__ __nv_bfloat16 g_ql[4096 * 256];
__device__ __nv_bfloat16 g_Mth[512 * 256];
__device__ __nv_bfloat16 g_Mtl[512 * 256];
__device__ __nv_bfloat16 g_Pth[256 * 512];
__device__ __nv_bfloat16 g_Ptl[256 * 512];
__device__ __nv_bfloat16 g_kbh[4096 * 512];
__device__ __nv_bfloat16 g_kbl[4096 * 512];
__device__ float g_qk[4096 * 512];
__device__ float g_x[4096 * 256];

__device__ __forceinline__ ull pk2(float x) {
  ull r; asm("mov.b64 %0,{%1,%1};" : "=l"(r) : "f"(x)); return r;
}
__device__ __forceinline__ void fma2(ull& d, ull a, ull b) {
  asm("fma.rn.f32x2 %0,%1,%2,%0;" : "+l"(d) : "l"(a), "l"(b));
}
__device__ __forceinline__ float2 upk(ull v) {
  float2 f; asm("mov.b64 {%0,%1},%2;" : "=f"(f.x), "=f"(f.y) : "l"(v)); return f;
}
__device__ __forceinline__ u32 smem_to_u32(const void* smem_ptr) {
  u32 addr;
  asm("{ .reg .u64 tmp; cvta.to.shared.u64 tmp, %1; cvt.u32.u64 %0, tmp; }"
      : "=r"(addr) : "l"(smem_ptr));
  return addr;
}
__device__ __forceinline__ void bf16_split(float v, __nv_bfloat16* h, __nv_bfloat16* l) {
  __nv_bfloat16 hh = __float2bfloat16(v);
  *h = hh;
  *l = __float2bfloat16(v - __bfloat162float(hh));
}

#define LDSM4(r0, r1, r2, r3, addr) \
  asm volatile("ldmatrix.sync.aligned.m8n8.x4.shared.b16 {%0,%1,%2,%3}, [%4];" \
               : "=r"(r0), "=r"(r1), "=r"(r2), "=r"(r3) : "r"(addr))
#define LDSM2(r0, r1, addr) \
  asm volatile("ldmatrix.sync.aligned.m8n8.x2.shared.b16 {%0,%1}, [%2];" \
               : "=r"(r0), "=r"(r1) : "r"(addr))
#define MMA16816(c, a, b) \
  asm volatile("mma.sync.aligned.m16n8k16.row.col.f32.bf16.bf16.f32 " \
               "{%0,%1,%2,%3}, {%4,%5,%6,%7}, {%8,%9}, {%0,%1,%2,%3};" \
               : "+f"((c)[0]), "+f"((c)[1]), "+f"((c)[2]), "+f"((c)[3]) \
               : "r"((a)[0]), "r"((a)[1]), "r"((a)[2]), "r"((a)[3]), \
                 "r"((b)[0]), "r"((b)[1]))

// ---------------------------------------------------------------------------
// K0: precompute M^T, P^T as bf16 hi/lo.
// ---------------------------------------------------------------------------
__global__ __launch_bounds__(256) void k0_precompute(
    const float* __restrict__ w_qs, const float* __restrict__ w_ks,
    const float* __restrict__ w_vs, const float* __restrict__ fc_w) {
  extern __shared__ float s0[];
  float* As = s0;              // 64 x 132
  float* Bsm = s0 + 64 * 132;  // M: 64 x 132; P: 128 x 64
  int m = blockIdx.x, t = threadIdx.x;
  int ty = t >> 4, tx = t & 15;
  float acc[4][4] = {{0.f}};

  if (m < 32) {
    int h = m >> 4, kt = (m >> 2) & 3, ct = m & 3;
#pragma unroll
    for (int i = 0; i < 8; i++) {
      int e = t + i * 256, r = e >> 5, c4 = e & 31;
      *(float4*)&As[r * 132 + c4 * 4] =
          *(const float4*)&w_qs[(kt * 64 + r) * 256 + h * 128 + c4 * 4];
      *(float4*)&Bsm[r * 132 + c4 * 4] =
          *(const float4*)&w_ks[(ct * 64 + r) * 256 + h * 128 + c4 * 4];
    }
    __syncthreads();
    for (int d = 0; d < 128; d += 4) {
      float4 av[4], bv[4];
#pragma unroll
      for (int i = 0; i < 4; i++) { av[i] = *(const float4*)&As[(ty * 4 + i) * 132 + d]; }
#pragma unroll
      for (int j = 0; j < 4; j++) { bv[j] = *(const float4*)&Bsm[(tx * 4 + j) * 132 + d]; }
#pragma unroll
      for (int i = 0; i < 4; i++) {
#pragma unroll
        for (int j = 0; j < 4; j++) {
          acc[i][j] += av[i].x * bv[j].x + av[i].y * bv[j].y +
                       av[i].z * bv[j].z + av[i].w * bv[j].w;
        }
      }
    }
#pragma unroll
    for (int i = 0; i < 4; i++) {
#pragma unroll
      for (int j = 0; j < 4; j++) {
        int kg = kt * 64 + ty * 4 + i;
        int ng = h * 256 + ct * 64 + tx * 4 + j;
        bf16_split(acc[i][j], &g_Mth[ng * 256 + kg], &g_Mtl[ng * 256 + kg]);
      }
    }
  } else {
    int m2 = m - 32;
    int h = m2 >> 4, it = (m2 >> 2) & 3, jt = m2 & 3;
#pragma unroll
    for (int i = 0; i < 8; i++) {
      int e = t + i * 256, r = e >> 5, c4 = e & 31;
      *(float4*)&As[r * 132 + c4 * 4] =
          *(const float4*)&w_vs[(it * 64 + r) * 256 + h * 128 + c4 * 4];
    }
#pragma unroll
    for (int i = 0; i < 8; i++) {
      int e = t + i * 256, d = e >> 4, j4 = e & 15;
      *(float4*)&Bsm[d * 64 + j4 * 4] =
          *(const float4*)&fc_w[(h * 128 + d) * 256 + jt * 64 + j4 * 4];
    }
    __syncthreads();
    for (int d = 0; d < 128; d++) {
      float4 bv = *(const float4*)&Bsm[d * 64 + tx * 4];
      float av[4];
#pragma unroll
      for (int i = 0; i < 4; i++) { av[i] = As[(ty * 4 + i) * 132 + d]; }
#pragma unroll
      for (int i = 0; i < 4; i++) {
        acc[i][0] += av[i] * bv.x; acc[i][1] += av[i] * bv.y;
        acc[i][2] += av[i] * bv.z; acc[i][3] += av[i] * bv.w;
      }
    }
#pragma unroll
    for (int i = 0; i < 4; i++) {
#pragma unroll
      for (int j = 0; j < 4; j++) {
        int kg = h * 256 + it * 64 + ty * 4 + i;
        int ng = jt * 64 + tx * 4 + j;
        bf16_split(acc[i][j], &g_Pth[ng * 512 + kg], &g_Ptl[ng * 512 + kg]);
      }
    }
  }
}

// ---------------------------------------------------------------------------
// K0b: q_in -> bf16 hi/lo.
// ---------------------------------------------------------------------------
__global__ __launch_bounds__(256) void k0b_convq(const float* __restrict__ src,
                                                 const float* __restrict__ srct) {
  int idx = blockIdx.x * 256 + threadIdx.x;
  int b = idx >> 8, k = idx & 255;
  float v = (k < 128) ? src[b * 128 + k] : srct[b * 128 + k - 128];
  bf16_split(v, &g_qh[idx], &g_ql[idx]);
}

// ---------------------------------------------------------------------------
// KG: bf16-split warp-MMA GEMM. CTA tile 64x64, warp tile 32x32 (2x2 warps),
// K-chunks of 32, 128 threads. C[M,N] = A[M,K]@B[N,K]^T.
// ---------------------------------------------------------------------------
__global__ __launch_bounds__(128) void kg_wmma(
    const __nv_bfloat16* __restrict__ Ah, const __nv_bfloat16* __restrict__ Al,
    const __nv_bfloat16* __restrict__ Bh, const __nv_bfloat16* __restrict__ Bl,
    float* __restrict__ C, int K, int Nld) {
  __shared__ __nv_bfloat16 sAh[64 * 40];
  __shared__ __nv_bfloat16 sAl[64 * 40];
  __shared__ __nv_bfloat16 sBh[64 * 40];
  __shared__ __nv_bfloat16 sBl[64 * 40];
  int t = threadIdx.x, lane = t & 31, wid = t >> 5;
  int wm = wid >> 1, wn = wid & 1;  // warp grid 2 x 2
  int bm = blockIdx.x * 64, bn = blockIdx.y * 64;
  u32 baAh = smem_to_u32(sAh), baAl = smem_to_u32(sAl);
  u32 baBh = smem_to_u32(sBh), baBl = smem_to_u32(sBl);

  float c[2][4][4];
#pragma unroll
  for (int mi = 0; mi < 2; mi++) {
#pragma unroll
    for (int ni = 0; ni < 4; ni++) {
#pragma unroll
      for (int q = 0; q < 4; q++) { c[mi][ni][q] = 0.f; }
    }
  }

  uint4 pAh[2], pAl[2], pBh[2], pBl[2];
  int nch = K >> 5;

  // prefetch chunk 0: each tensor tile is 64 rows x 32 cols bf16 (4 KB)
#pragma unroll
  for (int i = 0; i < 2; i++) {
    int e = t + i * 128, r = e >> 2, q = e & 3;
    pAh[i] = *(const uint4*)(Ah + (size_t)(bm + r) * K + q * 8);
    pAl[i] = *(const uint4*)(Al + (size_t)(bm + r) * K + q * 8);
    pBh[i] = *(const uint4*)(Bh + (size_t)(bn + r) * K + q * 8);
    pBl[i] = *(const uint4*)(Bl + (size_t)(bn + r) * K + q * 8);
  }

  for (int ch = 0; ch < nch; ch++) {
#pragma unroll
    for (int i = 0; i < 2; i++) {
      int e = t + i * 128, r = e >> 2, q = e & 3;
      *(uint4*)(sAh + r * 40 + q * 8) = pAh[i];
      *(uint4*)(sAl + r * 40 + q * 8) = pAl[i];
      *(uint4*)(sBh + r * 40 + q * 8) = pBh[i];
      *(uint4*)(sBl + r * 40 + q * 8) = pBl[i];
    }
    __syncthreads();
    if (ch + 1 < nch) {
#pragma unroll
      for (int i = 0; i < 2; i++) {
        int e = t + i * 128, r = e >> 2, q = e & 3;
        pAh[i] = *(const uint4*)(Ah + (size_t)(bm + r) * K + (ch + 1) * 32 + q * 8);
        pAl[i] = *(const uint4*)(Al + (size_t)(bm + r) * K + (ch + 1) * 32 + q * 8);
        pBh[i] = *(const uint4*)(Bh + (size_t)(bn + r) * K + (ch + 1) * 32 + q * 8);
        pBl[i] = *(const uint4*)(Bl + (size_t)(bn + r) * K + (ch + 1) * 32 + q * 8);
      }
    }
#pragma unroll
    for (int ks = 0; ks < 2; ks++) {
      u32 bro = (u32)((lane & 7) * 80 + ks * 32 + ((lane >> 3) & 1) * 16);
      u32 bh[4][2], bl[4][2];
#pragma unroll
      for (int ni = 0; ni < 4; ni++) {
        u32 boff = (u32)((wn * 32 + ni * 8) * 80) + bro;
        LDSM2(bh[ni][0], bh[ni][1], baBh + boff);
        LDSM2(bl[ni][0], bl[ni][1], baBl + boff);
      }
#pragma unroll
      for (int mi = 0; mi < 2; mi++) {
        u32 aro = (u32)((wm * 32 + mi * 16 + (lane & 15)) * 80 + ks * 32 +
                        (lane >> 4) * 16);
        u32 ah[4], al[4];
        LDSM4(ah[0], ah[1], ah[2], ah[3], baAh + aro);
        LDSM4(al[0], al[1], al[2], al[3], baAl + aro);
#pragma unroll
        for (int ni = 0; ni < 4; ni++) {
          MMA16816(c[mi][ni], ah, bh[ni]);
          MMA16816(c[mi][ni], ah, bl[ni]);
          MMA16816(c[mi][ni], al, bh[ni]);
        }
      }
    }
    __syncthreads();
  }

#pragma unroll
  for (int mi = 0; mi < 2; mi++) {
#pragma unroll
    for (int ni = 0; ni < 4; ni++) {
      int row0 = bm + wm * 32 + mi * 16 + (lane >> 2);
      int col = bn + wn * 32 + ni * 8 + (lane & 3) * 2;
      float2 v0 = make_float2(c[mi][ni][0], c[mi][ni][1]);
      float2 v1 = make_float2(c[mi][ni][2], c[mi][ni][3]);
      *(float2*)&C[(size_t)row0 * Nld + col] = v0;
      *(float2*)&C[(size_t)(row0 + 8) * Nld + col] = v1;
    }
  }
}

// ---------------------------------------------------------------------------
// K2: attention, single-pass, keys front-batched into registers (MLP=16).
// (R13 version — measured best.)
// ---------------------------------------------------------------------------
__global__ __launch_bounds__(256) void k2_attn(const float* __restrict__ seq,
                                               const float* __restrict__ seqt,
                                               const void* __restrict__ maskp,
                                               float* __restrict__ out) {
  __shared__ float red[8 * 512];
  __shared__ float aw[128];
  __shared__ float mflag[64];
  __shared__ int smode;

  int b = blockIdx.x, t = threadIdx.x;
  int w = t >> 5, l = t & 31;

  const float4* s4 = (const float4*)(seq + (long long)b * 8192);
  const float4* st4 = (const float4*)(seqt + (long long)b * 8192);
  float4 kA[8], kB[8];
#pragma unroll
  for (int i = 0; i < 8; i++) { kA[i] = s4[t + i * 256]; }
#pragma unroll
  for (int i = 0; i < 8; i++) { kB[i] = st4[t + i * 256]; }

  const float4* qv = (const float4*)(g_qk + b * 512);
  float4 qA0 = qv[l], qB0 = qv[32 + l], qA1 = qv[64 + l], qB1 = qv[96 + l];

  if (t == 0) {
    const unsigned int* mw = (const unsigned int*)maskp;
    int isInt = 1, isFloat = 1;
    for (int i = 0; i < 32; i++) {
      unsigned v = mw[i];
      if (v > 1u) { isInt = 0; }
      if (v != 0u && v != 0x3F800000u) { isFloat = 0; }
    }
    smode = isInt ? 0 : (isFloat ? 1 : 2);
  }
  __syncthreads();
  if (t < 64) {
    int mode = smode, m;
    if (mode == 0)      { m = ((const int*)maskp)[b * 64 + t] != 0; }
    else if (mode == 1) { m = ((const float*)maskp)[b * 64 + t] != 0.f; }
    else                { m = ((const unsigned char*)maskp)[b * 64 + t] != 0; }
    mflag[t] = m ? 1.f : 0.f;
  }
  __syncthreads();

  const float sc = 0.08838834764831843f;
#pragma unroll
  for (int i = 0; i < 8; i++) {
    float s0 = kA[i].x * qA0.x + kA[i].y * qA0.y + kA[i].z * qA0.z + kA[i].w * qA0.w +
               kB[i].x * qB0.x + kB[i].y * qB0.y + kB[i].z * qB0.z + kB[i].w * qB0.w;
    float s1 = kA[i].x * qA1.x + kA[i].y * qA1.y + kA[i].z * qA1.z + kA[i].w * qA1.w +
               kB[i].x * qB1.x + kB[i].y * qB1.y + kB[i].z * qB1.z + kB[i].w * qB1.w;
#pragma unroll
    for (int o = 16; o; o >>= 1) {
      s0 += __shfl_xor_sync(0xffffffffu, s0, o);
      s1 += __shfl_xor_sync(0xffffffffu, s1, o);
    }
    if (l == 0) {
      int n = w + 8 * i;
      int masked = (mflag[n] != 0.f);
      aw[n] = masked ? -1e10f : s0 * sc;
      aw[64 + n] = masked ? -1e10f : s1 * sc;
    }
  }
  __syncthreads();

  if (w < 2) {
    float x0 = aw[w * 64 + l], x1 = aw[w * 64 + 32 + l];
    float m = fmaxf(x0, x1);
#pragma unroll
    for (int o = 16; o; o >>= 1) { m = fmaxf(m, __shfl_xor_sync(0xffffffffu, m, o)); }
    float e0 = __expf(x0 - m), e1 = __expf(x1 - m);
    float s = e0 + e1;
#pragma unroll
    for (int o = 16; o; o >>= 1) { s += __shfl_xor_sync(0xffffffffu, s, o); }
    float inv = 1.f / s;
    float a0 = e0 * inv, a1 = e1 * inv;
    aw[w * 64 + l] = a0;
    aw[w * 64 + 32 + l] = a1;
    out[524288 + (w * 4096 + b) * 64 + l] = a0;
    out[524288 + (w * 4096 + b) * 64 + 32 + l] = a1;
  }
  __syncthreads();

  float4 aA0 = {0, 0, 0, 0}, aB0 = {0, 0, 0, 0};
  float4 aA1 = {0, 0, 0, 0}, aB1 = {0, 0, 0, 0};
#pragma unroll
  for (int i = 0; i < 8; i++) {
    int n = w + 8 * i;
    float a0 = aw[n], a1 = aw[64 + n];
    aA0.x += a0 * kA[i].x; aA0.y += a0 * kA[i].y; aA0.z += a0 * kA[i].z; aA0.w += a0 * kA[i].w;
    aB0.x += a0 * kB[i].x; aB0.y += a0 * kB[i].y; aB0.z += a0 * kB[i].z; aB0.w += a0 * kB[i].w;
    aA1.x += a1 * kA[i].x; aA1.y += a1 * kA[i].y; aA1.z += a1 * kA[i].z; aA1.w += a1 * kA[i].w;
    aB1.x += a1 * kB[i].x; aB1.y += a1 * kB[i].y; aB1.z += a1 * kB[i].z; aB1.w += a1 * kB[i].w;
  }
  *(float4*)&red[w * 512 + 4 * l] = aA0;
  *(float4*)&red[w * 512 + 128 + 4 * l] = aB0;
  *(float4*)&red[w * 512 + 256 + 4 * l] = aA1;
  *(float4*)&red[w * 512 + 384 + 4 * l] = aB1;
  __syncthreads();

  float kb0 = 0.f, kb1 = 0.f;
#pragma unroll
  for (int j = 0; j < 8; j++) {
    kb0 += red[j * 512 + t];
    kb1 += red[j * 512 + 256 + t];
  }
  bf16_split(kb0, &g_kbh[b * 512 + t], &g_kbl[b * 512 + t]);
  bf16_split(kb1, &g_kbh[b * 512 + 256 + t], &g_kbl[b * 512 + 256 + t]);
}

// ---------------------------------------------------------------------------
// K3b: per 16-batch tile: g_x + fc_b + residual -> LN -> FFN -> out.
// ---------------------------------------------------------------------------
__global__ __launch_bounds__(256) void k3b_ffn(
    const float* __restrict__ src, const float* __restrict__ srct,
    const float* __restrict__ fc_b, const float* __restrict__ ln_g,
    const float* __restrict__ ln_b, const float* __restrict__ fc1_w,
    const float* __restrict__ fc1_b, const float* __restrict__ fc2_w,
    const float* __restrict__ fc2_b, float* __restrict__ out) {
  extern __shared__ float sm3[];
  float* xh = sm3;           // 16 x 388
  float* Bs = xh + 16 * 388; // 32 x 128
  float* hm = Bs + 4096;     // 16 x 132
  int bb = blockIdx.x * 16;
  int t = threadIdx.x;
  int w = t >> 5, l = t & 31;

#pragma unroll
  for (int i = 0; i < 4; i++) {
    int e = t + i * 256, r = e >> 6, c4 = e & 63;
    int gb = bb + r;
    float4 a = *(const float4*)&g_x[gb * 256 + c4 * 4];
    float4 fb = *(const float4*)&fc_b[c4 * 4];
    float4 rs = (c4 < 32) ? *(const float4*)&src[gb * 128 + c4 * 4]
                          : *(const float4*)&srct[gb * 128 + (c4 - 32) * 4];
    xh[r * 388 + c4 * 4 + 0] = a.x + fb.x + rs.x;
    xh[r * 388 + c4 * 4 + 1] = a.y + fb.y + rs.y;
    xh[r * 388 + c4 * 4 + 2] = a.z + fb.z + rs.z;
    xh[r * 388 + c4 * 4 + 3] = a.w + fb.w + rs.w;
  }
#pragma unroll
  for (int i = 0; i < 2; i++) {
    int e = t + i * 256, r = e >> 5, c4 = e & 31;
    *(float4*)&xh[r * 388 + 256 + c4 * 4] = *(const float4*)&src[(bb + r) * 128 + c4 * 4];
  }
  __syncthreads();

#pragma unroll
  for (int rr = 0; rr < 2; rr++) {
    int r = w * 2 + rr;
    float s1 = 0.f, s2 = 0.f;
#pragma unroll
    for (int q = 0; q < 8; q++) {
      float x = xh[r * 388 + l + 32 * q];
      s1 += x; s2 += x * x;
    }
#pragma unroll
    for (int o = 16; o; o >>= 1) {
      s1 += __shfl_xor_sync(0xffffffffu, s1, o);
      s2 += __shfl_xor_sync(0xffffffffu, s2, o);
    }
    float mu = s1 * (1.f / 256.f);
    float var = s2 * (1.f / 256.f) - mu * mu;
    float rs = rsqrtf(var + 1e-5f);
#pragma unroll
    for (int q = 0; q < 8; q++) {
      int c = l + 32 * q;
      float x = xh[r * 388 + c];
      xh[r * 388 + c] = (x - mu) * rs * ln_g[c] + ln_b[c];
    }
  }
  __syncthreads();

  int ty2 = w, tx2 = l;
  {
    ull acc00 = 0ull, acc01 = 0ull, acc10 = 0ull, acc11 = 0ull;
    float4 pb[4];
#pragma unroll
    for (int i = 0; i < 4; i++) {
      int e = t + i * 256, kk = e >> 5, c4 = e & 31;
      pb[i] = *(const float4*)&fc1_w[kk * 128 + c4 * 4];
    }
    for (int kt = 0; kt < 12; kt++) {
#pragma unroll
      for (int i = 0; i < 4; i++) {
        int e = t + i * 256, kk = e >> 5, c4 = e & 31;
        *(float4*)&Bs[kk * 128 + c4 * 4] = pb[i];
      }
      __syncthreads();
      if (kt < 11) {
#pragma unroll
        for (int i = 0; i < 4; i++) {
          int e = t + i * 256, kk = e >> 5, c4 = e & 31;
          pb[i] = *(const float4*)&fc1_w[((kt + 1) * 32 + kk) * 128 + c4 * 4];
        }
      }
#pragma unroll
      for (int kk = 0; kk < 32; kk++) {
        int k = kt * 32 + kk;
        ull A0 = pk2(xh[(ty2 * 2 + 0) * 388 + k]);
        ull A1 = pk2(xh[(ty2 * 2 + 1) * 388 + k]);
        ull b0 = *(const ull*)&Bs[kk * 128 + tx2 * 4];
        ull b1 = *(const ull*)&Bs[kk * 128 + tx2 * 4 + 2];
        fma2(acc00, A0, b0); fma2(acc01, A0, b1);
        fma2(acc10, A1, b0); fma2(acc11, A1, b1);
      }
      __syncthreads();
    }
    {
      float2 p0 = upk(acc00), p1 = upk(acc01);
      float2 p2 = upk(acc10), p3 = upk(acc11);
      int c = tx2 * 4;
      hm[(ty2 * 2 + 0) * 132 + c + 0] = fmaxf(p0.x + fc1_b[c + 0], 0.f);
      hm[(ty2 * 2 + 0) * 132 + c + 1] = fmaxf(p0.y + fc1_b[c + 1], 0.f);
      hm[(ty2 * 2 + 0) * 132 + c + 2] = fmaxf(p1.x + fc1_b[c + 2], 0.f);
      hm[(ty2 * 2 + 0) * 132 + c + 3] = fmaxf(p1.y + fc1_b[c + 3], 0.f);
      hm[(ty2 * 2 + 1) * 132 + c + 0] = fmaxf(p2.x + fc1_b[c + 0], 0.f);
      hm[(ty2 * 2 + 1) * 132 + c + 1] = fmaxf(p2.y + fc1_b[c + 1], 0.f);
      hm[(ty2 * 2 + 1) * 132 + c + 2] = fmaxf(p3.x + fc1_b[c + 2], 0.f);
      hm[(ty2 * 2 + 1) * 132 + c + 3] = fmaxf(p3.y + fc1_b[c + 3], 0.f);
    }
  }
  __syncthreads();

  {
    ull acc00 = 0ull, acc01 = 0ull, acc10 = 0ull, acc11 = 0ull;
    float4 pb[4];
#pragma unroll
    for (int i = 0; i < 4; i++) {
      int e = t + i * 256, kk = e >> 5, c4 = e & 31;
      pb[i] = *(const float4*)&fc2_w[kk * 128 + c4 * 4];
    }
    for (int kt = 0; kt < 4; kt++) {
#pragma unroll
      for (int i = 0; i < 4; i++) {
        int e = t + i * 256, kk = e >> 5, c4 = e & 31;
        *(float4*)&Bs[kk * 128 + c4 * 4] = pb[i];
      }
      __syncthreads();
      if (kt < 3) {
#pragma unroll
        for (int i = 0; i < 4; i++) {
          int e = t + i * 256, kk = e >> 5, c4 = e & 31;
          pb[i] = *(const float4*)&fc2_w[((kt + 1) * 32 + kk) * 128 + c4 * 4];
        }
      }
#pragma unroll
      for (int kk = 0; kk < 32; kk++) {
        int k = kt * 32 + kk;
        ull A0 = pk2(hm[(ty2 * 2 + 0) * 132 + k]);
        ull A1 = pk2(hm[(ty2 * 2 + 1) * 132 + k]);
        ull b0 = *(const ull*)&Bs[kk * 128 + tx2 * 4];
        ull b1 = *(const ull*)&Bs[kk * 128 + tx2 * 4 + 2];
        fma2(acc00, A0, b0); fma2(acc01, A0, b1);
        fma2(acc10, A1, b0); fma2(acc11, A1, b1);
      }
      __syncthreads();
    }
    {
      float2 p0 = upk(acc00), p1 = upk(acc01);
      float2 p2 = upk(acc10), p3 = upk(acc11);
      int c = tx2 * 4;
      int r0 = bb + ty2 * 2 + 0, r1 = bb + ty2 * 2 + 1;
      float4 v0 = make_float4(p0.x + fc2_b[c], p0.y + fc2_b[c + 1],
                              p1.x + fc2_b[c + 2], p1.y + fc2_b[c + 3]);
      float4 v1 = make_float4(p2.x + fc2_b[c], p2.y + fc2_b[c + 1],
                              p3.x + fc2_b[c + 2], p3.y + fc2_b[c + 3]);
      *(float4*)&out[r0 * 128 + c] = v0;
      *(float4*)&out[r1 * 128 + c] = v1;
    }
  }
}

// ---------------------------------------------------------------------------
extern "C" void kernel_launch(void* const* d_in, const int* in_sizes, int n_in,
                              void* d_out, int out_size) {
  const float* src   = (const float*)d_in[0];
  const float* src_t = (const float*)d_in[1];
  const float* seq   = (const float*)d_in[2];
  const float* seq_t = (const float*)d_in[3];
  const void*  mask  = d_in[4];
  const float* w_qs  = (const float*)d_in[5];
  const float* w_ks  = (const float*)d_in[6];
  const float* w_vs  = (const float*)d_in[7];
  const float* fc_w  = (const float*)d_in[8];
  const float* fc_b  = (const float*)d_in[9];
  const float* ln_g  = (const float*)d_in[10];
  const float* ln_b  = (const float*)d_in[11];
  const float* fc1_w = (const float*)d_in[12];
  const float* fc1_b = (const float*)d_in[13];
  const float* fc2_w = (const float*)d_in[14];
  const float* fc2_b = (const float*)d_in[15];
  float* out = (float*)d_out;

  const int K0_SMEM = (64 * 132 * 2) * 4;
  const int K3B_SMEM = (16 * 388 + 4096 + 16 * 132) * 4;
  cudaFuncSetAttribute(k0_precompute, cudaFuncAttributeMaxDynamicSharedMemorySize, K0_SMEM);
  cudaFuncSetAttribute(k3b_ffn, cudaFuncAttributeMaxDynamicSharedMemorySize, K3B_SMEM);

  __nv_bfloat16 *qh, *ql, *Mth, *Mtl, *Pth, *Ptl, *kbh, *kbl;
  float *qk, *xx;
  cudaGetSymbolAddress((void**)&qh, g_qh);
  cudaGetSymbolAddress((void**)&ql, g_ql);
  cudaGetSymbolAddress((void**)&Mth, g_Mth);
  cudaGetSymbolAddress((void**)&Mtl, g_Mtl);
  cudaGetSymbolAddress((void**)&Pth, g_Pth);
  cudaGetSymbolAddress((void**)&Ptl, g_Ptl);
  cudaGetSymbolAddress((void**)&kbh, g_kbh);
  cudaGetSymbolAddress((void**)&kbl, g_kbl);
  cudaGetSymbolAddress((void**)&qk, g_qk);
  cudaGetSymbolAddress((void**)&xx, g_x);

  k0_precompute<<<64, 256, K0_SMEM>>>(w_qs, w_ks, w_vs, fc_w);
  k0b_convq<<<4096, 256>>>(src, src_t);
  // K1: qk[4096,512] = q[4096,256] @ Mt[512,256]^T  -> grid (64, 8)
  kg_wmma<<<dim3(64, 8), 128>>>(qh, ql, Mth, Mtl, qk, 256, 512);
  k2_attn<<<4096, 256>>>(seq, seq_t, mask, out);
  // K3a: x[4096,256] = kbar[4096,512] @ Pt[256,512]^T -> grid (64, 4)
  kg_wmma<<<dim3(64, 4), 128>>>(kbh, kbl, Pth, Ptl, xx, 512, 256);
  k3b_ffn<<<256, 256, K3B_SMEM>>>(src, src_t, fc_b, ln_g, ln_b, fc1_w, fc1_b,
                                  fc2_w, fc2_b, out);
}